// round 1
// baseline (speedup 1.0000x reference)
#include <cuda_runtime.h>

#define N_NODES 100000
#define N_FEATS 512
#define HIDDEN  64
#define NSAMP   5
#define NCLS    16
#define NBATCH  16384

// Scratch (static device globals: allocation-free per harness rules)
__device__ float g_W1T[N_FEATS * 128];            // [512][128]: col n<64 -> w1 self part, n>=64 -> w1 neigh part
__device__ float g_W2T[HIDDEN * 128];             // [64][128]
__device__ float g_PG[(size_t)N_NODES * 128];     // P (cols 0..63) | G (cols 64..127)
__device__ float g_h1[(size_t)N_NODES * HIDDEN];  // layer-1 activations
__device__ float g_UV[(size_t)N_NODES * 128];     // U (cols 0..63) | V (cols 64..127)

// ---------------------------------------------------------------------------
// Repack w1 [64,1024] and w2 [64,128] into k-major [K][128] operand matrices.
// ---------------------------------------------------------------------------
__global__ void prep_weights(const float* __restrict__ w1, const float* __restrict__ w2) {
    int idx = blockIdx.x * blockDim.x + threadIdx.x;
    if (idx < N_FEATS * 128) {
        int k = idx >> 7, n = idx & 127;
        g_W1T[idx] = (n < HIDDEN) ? w1[n * (2 * N_FEATS) + k]
                                  : w1[(n - HIDDEN) * (2 * N_FEATS) + N_FEATS + k];
    }
    if (idx < HIDDEN * 128) {
        int k = idx >> 7, n = idx & 127;
        g_W2T[idx] = (n < HIDDEN) ? w2[n * (2 * HIDDEN) + k]
                                  : w2[(n - HIDDEN) * (2 * HIDDEN) + HIDDEN + k];
    }
}

// ---------------------------------------------------------------------------
// SGEMM: C[M,128] = A[M,K] @ B[K,128]. 128x128 CTA tile, 8x8 per thread,
// 32-deep k-chunks. K is 512 (layer 1) or 64 (layer 2).
// ---------------------------------------------------------------------------
template <int K>
__global__ __launch_bounds__(256, 2)
void gemm_n128(const float* __restrict__ A, const float* __restrict__ Bm,
               float* __restrict__ Cm, int M) {
    __shared__ float As[32][132];   // [k][row], padded
    __shared__ float Bs[32][132];   // [k][col], padded

    const int tid = threadIdx.x;
    const int tx = tid & 15;        // col group
    const int ty = tid >> 4;        // row group
    const int row0 = blockIdx.x * 128;

    float acc[8][8];
#pragma unroll
    for (int i = 0; i < 8; i++)
#pragma unroll
        for (int j = 0; j < 8; j++) acc[i][j] = 0.f;

    for (int k0 = 0; k0 < K; k0 += 32) {
        // Load A tile: 128 rows x 32 k = 1024 float4 -> 4 passes
#pragma unroll
        for (int p = 0; p < 4; p++) {
            int e  = p * 256 + tid;       // float4 index, 8 per row
            int r  = e >> 3;
            int kc = (e & 7) << 2;
            int gr = row0 + r;
            float4 v = make_float4(0.f, 0.f, 0.f, 0.f);
            if (gr < M) v = *(const float4*)(A + (size_t)gr * K + k0 + kc);
            As[kc + 0][r] = v.x; As[kc + 1][r] = v.y;
            As[kc + 2][r] = v.z; As[kc + 3][r] = v.w;
        }
        // Load B tile: 32 k-rows x 128 cols = 1024 float4 -> 4 passes
#pragma unroll
        for (int p = 0; p < 4; p++) {
            int e  = p * 256 + tid;
            int kr = e >> 5;
            int nc = (e & 31) << 2;
            *(float4*)&Bs[kr][nc] = *(const float4*)(Bm + (size_t)(k0 + kr) * 128 + nc);
        }
        __syncthreads();

#pragma unroll
        for (int k = 0; k < 32; k++) {
            float4 a0 = *(const float4*)&As[k][ty * 8];
            float4 a1 = *(const float4*)&As[k][ty * 8 + 4];
            float4 b0 = *(const float4*)&Bs[k][tx * 8];
            float4 b1 = *(const float4*)&Bs[k][tx * 8 + 4];
            float a[8] = {a0.x, a0.y, a0.z, a0.w, a1.x, a1.y, a1.z, a1.w};
            float b[8] = {b0.x, b0.y, b0.z, b0.w, b1.x, b1.y, b1.z, b1.w};
#pragma unroll
            for (int i = 0; i < 8; i++)
#pragma unroll
                for (int j = 0; j < 8; j++)
                    acc[i][j] = fmaf(a[i], b[j], acc[i][j]);
        }
        __syncthreads();
    }

#pragma unroll
    for (int i = 0; i < 8; i++) {
        int gr = row0 + ty * 8 + i;
        if (gr < M) {
            *(float4*)(Cm + (size_t)gr * 128 + tx * 8) =
                make_float4(acc[i][0], acc[i][1], acc[i][2], acc[i][3]);
            *(float4*)(Cm + (size_t)gr * 128 + tx * 8 + 4) =
                make_float4(acc[i][4], acc[i][5], acc[i][6], acc[i][7]);
        }
    }
}

// ---------------------------------------------------------------------------
// Layer-1 aggregation in 64-dim space:
//   h1[n] = relu(P[n] + 0.2 * sum_s G[neigh[n,s]])
// One warp per node; each lane owns 2 hidden dims.
// ---------------------------------------------------------------------------
__global__ void aggregate1_kernel(const int* __restrict__ neigh) {
    int gw   = (blockIdx.x * 256 + threadIdx.x) >> 5;
    int lane = threadIdx.x & 31;
    if (gw >= N_NODES) return;

    const float* base = g_PG + (size_t)gw * 128;
    float2 s = *(const float2*)(base + lane * 2);
    float ax = 0.f, ay = 0.f;
#pragma unroll
    for (int j = 0; j < NSAMP; j++) {
        int nb = __ldg(&neigh[gw * NSAMP + j]);
        float2 v = *(const float2*)(g_PG + (size_t)nb * 128 + 64 + lane * 2);
        ax += v.x; ay += v.y;
    }
    float hx = fmaxf(fmaf(ax, 0.2f, s.x), 0.f);
    float hy = fmaxf(fmaf(ay, 0.2f, s.y), 0.f);
    *(float2*)(g_h1 + (size_t)gw * 64 + lane * 2) = make_float2(hx, hy);
}

// ---------------------------------------------------------------------------
// Final: per batch element b (4 per CTA, 64 threads each):
//   n = nodes[b]; h2 = relu(U[n] + 0.2 * sum_s V[neigh[n,s]]); out = h2 @ w_cls.T
// ---------------------------------------------------------------------------
__global__ __launch_bounds__(256)
void final_kernel(const int* __restrict__ nodes, const int* __restrict__ neigh,
                  const float* __restrict__ wcls, float* __restrict__ out) {
    __shared__ float h2s[4][64];
    __shared__ float wcs[16][66];   // padded to kill bank conflicts

    int tid = threadIdx.x;
    for (int i = tid; i < NCLS * HIDDEN; i += 256)
        wcs[i >> 6][i & 63] = wcls[i];

    int sub = tid >> 6;          // 0..3  (batch element within CTA)
    int h   = tid & 63;          // hidden dim
    int b   = blockIdx.x * 4 + sub;

    float val = 0.f;
    if (b < NBATCH) {
        int n = nodes[b];
        float self = g_UV[(size_t)n * 128 + h];
        float acc = 0.f;
#pragma unroll
        for (int j = 0; j < NSAMP; j++) {
            int nb = __ldg(&neigh[n * NSAMP + j]);
            acc += g_UV[(size_t)nb * 128 + 64 + h];
        }
        val = fmaxf(fmaf(acc, 0.2f, self), 0.f);
    }
    h2s[sub][h] = val;
    __syncthreads();

    if (tid < 64) {
        int sub2 = tid >> 4;
        int c    = tid & 15;
        int b2   = blockIdx.x * 4 + sub2;
        if (b2 < NBATCH) {
            float acc = 0.f;
#pragma unroll
            for (int k = 0; k < HIDDEN; k++)
                acc = fmaf(wcs[c][k], h2s[sub2][k], acc);
            out[b2 * NCLS + c] = acc;
        }
    }
}

// ---------------------------------------------------------------------------
extern "C" void kernel_launch(void* const* d_in, const int* in_sizes, int n_in,
                              void* d_out, int out_size) {
    const float* features = (const float*)d_in[0];
    const float* w1       = (const float*)d_in[1];
    const float* w2       = (const float*)d_in[2];
    const float* wcls     = (const float*)d_in[3];
    const int*   nodes    = (const int*)d_in[4];
    const int*   neigh    = (const int*)d_in[5];
    float*       out      = (float*)d_out;

    float *pW1T, *pW2T, *pPG, *ph1, *pUV;
    cudaGetSymbolAddress((void**)&pW1T, g_W1T);
    cudaGetSymbolAddress((void**)&pW2T, g_W2T);
    cudaGetSymbolAddress((void**)&pPG,  g_PG);
    cudaGetSymbolAddress((void**)&ph1,  g_h1);
    cudaGetSymbolAddress((void**)&pUV,  g_UV);

    const int gemm_blocks = (N_NODES + 127) / 128;   // 782

    prep_weights<<<(N_FEATS * 128 + 255) / 256, 256>>>(w1, w2);
    gemm_n128<N_FEATS><<<gemm_blocks, 256>>>(features, pW1T, pPG, N_NODES);
    aggregate1_kernel<<<(N_NODES * 32 + 255) / 256, 256>>>(neigh);
    gemm_n128<HIDDEN><<<gemm_blocks, 256>>>(ph1, pW2T, pUV, N_NODES);
    final_kernel<<<(NBATCH + 3) / 4, 256>>>(nodes, neigh, wcls, out);
}